// round 3
// baseline (speedup 1.0000x reference)
#include <cuda_runtime.h>

// ---------------------------------------------------------------------------
// HeteroGAT — CSR-gather, 2-warp-per-node GAT, 128x64 FMA-bound GEMM
// ---------------------------------------------------------------------------

#define NAUT   16384
#define NPAP   16384
#define IN_DIM 128
#define HID    64
#define NHEAD  4
#define OUTF   349
#define NEDGE  262144
#define NNODE  16384
#define NEG_SLOPE 0.2f

constexpr long long NHF = (long long)NNODE * HID;
constexpr long long N4  = (long long)NNODE * NHEAD;

constexpr long long OFF_FA0   = 0;
constexpr long long OFF_FP0   = OFF_FA0 + NHF;
constexpr long long OFF_FP1   = OFF_FP0 + NHF;
constexpr long long OFF_FP2   = OFF_FP1 + NHF;
constexpr long long OFF_FA2   = OFF_FP2 + NHF;
constexpr long long OFF_F1A   = OFF_FA2 + NHF;
constexpr long long OFF_F1PD  = OFF_F1A + NHF;
constexpr long long OFF_F1PC  = OFF_F1PD + NHF;
constexpr long long OFF_OUTP  = OFF_F1PC + NHF;
constexpr long long OFF_OUTA  = OFF_OUTP + NHF;
constexpr long long OFF_OUTP1 = OFF_OUTA + NHF;
constexpr long long OFF_HA1   = OFF_OUTP1 + NHF;
constexpr long long OFF_HP1   = OFF_HA1 + NHF;
constexpr long long OFF_HF    = OFF_HP1 + NHF;
constexpr long long OFF_ELER  = OFF_HF + 2 * NHF;       // 10 x N4
constexpr long long OFF_C     = OFF_ELER + 10 * N4;
constexpr long long OFF_DEG   = OFF_C + 4;              // ints
constexpr long long OFF_RP    = OFF_DEG + 3LL * NNODE;
constexpr long long OFF_CSR   = OFF_RP + 3LL * (NNODE + 1);
constexpr long long SCRATCH_TOTAL = OFF_CSR + 3LL * NEDGE + 16;

__device__ float g_scratch[SCRATCH_TOTAL];

__device__ __forceinline__ float leaky(float x) {
    return x > 0.f ? x : NEG_SLOPE * x;
}

// ---------------------------------------------------------------------------
// CSR build
// ---------------------------------------------------------------------------
__global__ void zero_int_kernel(int* __restrict__ p, int n) {
    int i = blockIdx.x * blockDim.x + threadIdx.x;
    if (i < n) p[i] = 0;
}

__global__ void hist3_kernel(const int* __restrict__ d0, const int* __restrict__ d1,
                             const int* __restrict__ d2, int* __restrict__ deg) {
    int t = blockIdx.x * blockDim.x + threadIdx.x;
    if (t >= 3 * NEDGE) return;
    int g = t >> 18;
    int e = t & (NEDGE - 1);
    const int* ds = (g == 0) ? d0 : (g == 1) ? d1 : d2;
    atomicAdd(&deg[g * NNODE + ds[e]], 1);
}

__global__ __launch_bounds__(1024) void scan3_kernel(int* __restrict__ deg,
                                                     int* __restrict__ rp) {
    __shared__ int sh[1024];
    int t = threadIdx.x;
    int g = blockIdx.x;
    int* dg = deg + g * NNODE;
    int* r  = rp + g * (NNODE + 1);
    int loc[16];
    int run = 0;
    int base = t * 16;
#pragma unroll
    for (int i = 0; i < 16; i++) { loc[i] = run; run += dg[base + i]; }
    sh[t] = run;
    __syncthreads();
    for (int d = 1; d < 1024; d <<= 1) {
        int v = sh[t];
        int a = (t >= d) ? sh[t - d] : 0;
        __syncthreads();
        sh[t] = v + a;
        __syncthreads();
    }
    int off = (t == 0) ? 0 : sh[t - 1];
#pragma unroll
    for (int i = 0; i < 16; i++) {
        int v = off + loc[i];
        r[base + i] = v;
        dg[base + i] = v;
    }
    if (t == 1023) r[NNODE] = off + run;
}

__global__ void scatter3_kernel(const int* __restrict__ s0, const int* __restrict__ d0,
                                const int* __restrict__ s1, const int* __restrict__ d1,
                                const int* __restrict__ s2, const int* __restrict__ d2,
                                int* __restrict__ cur, int* __restrict__ csr) {
    int t = blockIdx.x * blockDim.x + threadIdx.x;
    if (t >= 3 * NEDGE) return;
    int g = t >> 18;
    int e = t & (NEDGE - 1);
    const int* ss = (g == 0) ? s0 : (g == 1) ? s1 : s2;
    const int* ds = (g == 0) ? d0 : (g == 1) ? d1 : d2;
    int d = ds[e];
    int pos = atomicAdd(&cur[g * NNODE + d], 1);
    csr[(long long)g * NEDGE + pos] = ss[e];
}

// ---------------------------------------------------------------------------
// Batched GEMM: C[16384,64] = (A .* colscale) @ W[K,64]
// 128x64 block tile, 8x4 per thread, K-tile 32. FMA-bound.
// ---------------------------------------------------------------------------
struct Gemm5 {
    const float* A[5];
    const float* scale[5];
    const float* W[5];
    float* C[5];
    int K;
};

__global__ __launch_bounds__(256) void gemm128_kernel(Gemm5 p) {
    int b = blockIdx.y;
    const float* A  = p.A[b];
    const float* sc = p.scale[b];
    const float* W  = p.W[b];
    float* C        = p.C[b];
    int K = p.K;
    __shared__ float As[128][33];       // [r][k], conflict-free
    __shared__ float Ws[32][64];        // [k][c]
    int row0 = blockIdx.x * 128;
    int tid = threadIdx.x;
    int tr = (tid >> 4) * 8;            // 0..120
    int tc = (tid & 15) * 4;            // 0..60
    float acc[8][4] = {};
    for (int kt = 0; kt < K; kt += 32) {
#pragma unroll
        for (int i = 0; i < 16; i++) {  // 4096 A elems
            int idx = tid + i * 256;
            int r = idx >> 5, k = idx & 31;
            float v = A[(long long)(row0 + r) * K + kt + k];
            if (sc) v *= sc[kt + k];
            As[r][k] = v;
        }
#pragma unroll
        for (int i = 0; i < 8; i++) {   // 2048 W elems
            int idx = tid + i * 256;
            int k = idx >> 6, c = idx & 63;
            Ws[k][c] = W[(long long)(kt + k) * 64 + c];
        }
        __syncthreads();
#pragma unroll
        for (int k = 0; k < 32; k++) {
            float4 w = *(const float4*)&Ws[k][tc];
            float a0 = As[tr + 0][k], a1 = As[tr + 1][k], a2 = As[tr + 2][k], a3 = As[tr + 3][k];
            float a4 = As[tr + 4][k], a5 = As[tr + 5][k], a6 = As[tr + 6][k], a7 = As[tr + 7][k];
            acc[0][0] += a0 * w.x; acc[0][1] += a0 * w.y; acc[0][2] += a0 * w.z; acc[0][3] += a0 * w.w;
            acc[1][0] += a1 * w.x; acc[1][1] += a1 * w.y; acc[1][2] += a1 * w.z; acc[1][3] += a1 * w.w;
            acc[2][0] += a2 * w.x; acc[2][1] += a2 * w.y; acc[2][2] += a2 * w.z; acc[2][3] += a2 * w.w;
            acc[3][0] += a3 * w.x; acc[3][1] += a3 * w.y; acc[3][2] += a3 * w.z; acc[3][3] += a3 * w.w;
            acc[4][0] += a4 * w.x; acc[4][1] += a4 * w.y; acc[4][2] += a4 * w.z; acc[4][3] += a4 * w.w;
            acc[5][0] += a5 * w.x; acc[5][1] += a5 * w.y; acc[5][2] += a5 * w.z; acc[5][3] += a5 * w.w;
            acc[6][0] += a6 * w.x; acc[6][1] += a6 * w.y; acc[6][2] += a6 * w.z; acc[6][3] += a6 * w.w;
            acc[7][0] += a7 * w.x; acc[7][1] += a7 * w.y; acc[7][2] += a7 * w.z; acc[7][3] += a7 * w.w;
        }
        __syncthreads();
    }
#pragma unroll
    for (int i = 0; i < 8; i++) {
        long long r = row0 + tr + i;
        float4 v = make_float4(acc[i][0], acc[i][1], acc[i][2], acc[i][3]);
        *(float4*)&C[r * 64 + tc] = v;
    }
}

// ---- full GEMM (bias, arbitrary Ncols) for the final projection ----
__global__ __launch_bounds__(256) void gemm_full_kernel(
    const float* __restrict__ A, const float* __restrict__ W,
    const float* __restrict__ bias, float* __restrict__ C,
    int K, int Ncols) {
    __shared__ float As[128][33];
    __shared__ float Ws[32][64];
    int row0 = blockIdx.x * 128;
    int col0 = blockIdx.y * 64;
    int tid = threadIdx.x;
    int tr = (tid >> 4) * 8;
    int tc = (tid & 15) * 4;
    float acc[8][4] = {};
    for (int kt = 0; kt < K; kt += 32) {
#pragma unroll
        for (int i = 0; i < 16; i++) {
            int idx = tid + i * 256;
            int r = idx >> 5, k = idx & 31;
            As[r][k] = A[(long long)(row0 + r) * K + kt + k];
        }
#pragma unroll
        for (int i = 0; i < 8; i++) {
            int idx = tid + i * 256;
            int k = idx >> 6, c = idx & 63;
            int gc = col0 + c;
            Ws[k][c] = (gc < Ncols) ? W[(long long)(kt + k) * Ncols + gc] : 0.0f;
        }
        __syncthreads();
#pragma unroll
        for (int k = 0; k < 32; k++) {
            float4 w = *(const float4*)&Ws[k][tc];
            float a0 = As[tr + 0][k], a1 = As[tr + 1][k], a2 = As[tr + 2][k], a3 = As[tr + 3][k];
            float a4 = As[tr + 4][k], a5 = As[tr + 5][k], a6 = As[tr + 6][k], a7 = As[tr + 7][k];
            acc[0][0] += a0 * w.x; acc[0][1] += a0 * w.y; acc[0][2] += a0 * w.z; acc[0][3] += a0 * w.w;
            acc[1][0] += a1 * w.x; acc[1][1] += a1 * w.y; acc[1][2] += a1 * w.z; acc[1][3] += a1 * w.w;
            acc[2][0] += a2 * w.x; acc[2][1] += a2 * w.y; acc[2][2] += a2 * w.z; acc[2][3] += a2 * w.w;
            acc[3][0] += a3 * w.x; acc[3][1] += a3 * w.y; acc[3][2] += a3 * w.z; acc[3][3] += a3 * w.w;
            acc[4][0] += a4 * w.x; acc[4][1] += a4 * w.y; acc[4][2] += a4 * w.z; acc[4][3] += a4 * w.w;
            acc[5][0] += a5 * w.x; acc[5][1] += a5 * w.y; acc[5][2] += a5 * w.z; acc[5][3] += a5 * w.w;
            acc[6][0] += a6 * w.x; acc[6][1] += a6 * w.y; acc[6][2] += a6 * w.z; acc[6][3] += a6 * w.w;
            acc[7][0] += a7 * w.x; acc[7][1] += a7 * w.y; acc[7][2] += a7 * w.z; acc[7][3] += a7 * w.w;
        }
        __syncthreads();
    }
#pragma unroll
    for (int i = 0; i < 8; i++) {
        long long r = row0 + tr + i;
#pragma unroll
        for (int j = 0; j < 4; j++) {
            int c = col0 + tc + j;
            if (c < Ncols) C[r * Ncols + c] = acc[i][j] + bias[c];
        }
    }
}

// ---------------------------------------------------------------------------
// Batched attention-logit halves
// ---------------------------------------------------------------------------
struct Eler6 {
    const float* F[6];
    const float* a[6];
    float* out[6];
};

__global__ void eler_kernel(Eler6 p) {
    int b = blockIdx.y;
    const float* F = p.F[b];
    const float* avec = p.a[b];
    float* out = p.out[b];
    int i = blockIdx.x * blockDim.x + threadIdx.x;
    if (i >= NNODE * NHEAD) return;
    int node = i >> 2, h = i & 3;
    const float4* f = (const float4*)(F + (long long)node * HID + h * 16);
    const float4* a = (const float4*)(avec + h * 16);
    float s = 0.f;
#pragma unroll
    for (int j = 0; j < 4; j++) {
        float4 fv = f[j], av = a[j];
        s += fv.x * av.x + fv.y * av.y + fv.z * av.z + fv.w * av.w;
    }
    out[i] = s;
}

// ---------------------------------------------------------------------------
// Fused GAT: TWO warps per destination node (one per 32-feature half).
// Online softmax in registers, unrolled x4 gather phase for MLP.
// ---------------------------------------------------------------------------
#define MERGE(m, s)                                                        \
    {                                                                      \
        float om = __shfl_xor_sync(0xFFFFFFFFu, (m), off);                 \
        float os = __shfl_xor_sync(0xFFFFFFFFu, (s), off);                 \
        float nm = fmaxf((m), om);                                         \
        (s) = (s) * __expf((m) - nm) + os * __expf(om - nm);               \
        (m) = nm;                                                          \
    }

__global__ __launch_bounds__(256) void gat_kernel(
    const int* __restrict__ rp, const int* __restrict__ csr,
    const float* __restrict__ el, const float* __restrict__ er,
    const float* __restrict__ fs, const float* __restrict__ prev,
    const float* __restrict__ ba, const float* __restrict__ bb,
    int do_relu, float* __restrict__ out) {
    int gw = (blockIdx.x * blockDim.x + threadIdx.x) >> 5;
    if (gw >= 2 * NNODE) return;
    int d = gw >> 1;
    int half = gw & 1;                 // 0: features 0-31 (heads 0,1); 1: 32-63 (heads 2,3)
    int lane = threadIdx.x & 31;
    int beg = rp[d], end = rp[d + 1];
    float4 er4 = *(const float4*)(er + 4 * d);
    float eA = half ? er4.z : er4.x;
    float eB = half ? er4.w : er4.y;

    // ---- phase A: online softmax stats for this half's 2 heads ----
    float mA = -1e30f, sA = 0.f, mB = -1e30f, sB = 0.f;
    for (int i = beg + lane; i < end; i += 32) {
        int s = csr[i];
        float4 l4 = *(const float4*)(el + 4 * s);
        float e0 = leaky((half ? l4.z : l4.x) + eA);
        float e1 = leaky((half ? l4.w : l4.y) + eB);
        float nm;
        nm = fmaxf(mA, e0); sA = sA * __expf(mA - nm) + __expf(e0 - nm); mA = nm;
        nm = fmaxf(mB, e1); sB = sB * __expf(mB - nm) + __expf(e1 - nm); mB = nm;
    }
#pragma unroll
    for (int off = 16; off; off >>= 1) { MERGE(mA, sA) MERGE(mB, sB) }
    float invA = 1.f / fmaxf(sA, 1e-9f);
    float invB = 1.f / fmaxf(sB, 1e-9f);

    // per-lane head selection within the half
    bool hiHead = (lane & 16) != 0;
    float m   = hiHead ? mB : mA;
    float inv = hiHead ? invB : invA;
    float e   = hiHead ? eB : eA;
    int fofs  = half * 32 + lane;

    // ---- phase B: weighted gather, unrolled x4 ----
    float acc = 0.f;
    int i = beg;
    for (; i + 4 <= end; i += 4) {
        int s0 = csr[i], s1 = csr[i + 1], s2 = csr[i + 2], s3 = csr[i + 3];
        float4 q0 = *(const float4*)(el + 4 * s0);
        float4 q1 = *(const float4*)(el + 4 * s1);
        float4 q2 = *(const float4*)(el + 4 * s2);
        float4 q3 = *(const float4*)(el + 4 * s3);
        float f0 = fs[(long long)s0 * HID + fofs];
        float f1 = fs[(long long)s1 * HID + fofs];
        float f2 = fs[(long long)s2 * HID + fofs];
        float f3 = fs[(long long)s3 * HID + fofs];
        float l0 = half ? (hiHead ? q0.w : q0.z) : (hiHead ? q0.y : q0.x);
        float l1 = half ? (hiHead ? q1.w : q1.z) : (hiHead ? q1.y : q1.x);
        float l2 = half ? (hiHead ? q2.w : q2.z) : (hiHead ? q2.y : q2.x);
        float l3 = half ? (hiHead ? q3.w : q3.z) : (hiHead ? q3.y : q3.x);
        acc += f0 * (__expf(leaky(l0 + e) - m) * inv);
        acc += f1 * (__expf(leaky(l1 + e) - m) * inv);
        acc += f2 * (__expf(leaky(l2 + e) - m) * inv);
        acc += f3 * (__expf(leaky(l3 + e) - m) * inv);
    }
    for (; i < end; i++) {
        int s = csr[i];
        float4 q = *(const float4*)(el + 4 * s);
        float l = half ? (hiHead ? q.w : q.z) : (hiHead ? q.y : q.x);
        acc += fs[(long long)s * HID + fofs] * (__expf(leaky(l + e) - m) * inv);
    }

    long long idx = (long long)d * HID + fofs;
    if (prev) acc += prev[idx];
    if (ba)   acc += ba[fofs];
    if (bb)   acc += bb[fofs];
    if (do_relu) acc = fmaxf(acc, 0.f);
    out[idx] = acc;
}

// ---------------------------------------------------------------------------
// Collapsed per-node transformer (size-1 feature axis => layernorm == bias)
// ---------------------------------------------------------------------------
__global__ void compute_C_kernel(const float* ln1_gb, const float* attn_w, const float* attn_b,
                                 const float* ln2_gb, const float* ffn_w1, const float* ffn_b1,
                                 const float* ffn_w2, const float* ffn_b2, float* out) {
    float y1 = ln1_gb[1];
    float v = y1 * attn_w[2] + attn_b[2];
    float o = v * attn_w[3] + attn_b[3];
    float y2 = ln2_gb[1];
    float f = ffn_b2[0];
    for (int j = 0; j < 16; j++) {
        float z = y2 * ffn_w1[j] + ffn_b1[j];
        float g = 0.5f * z * (1.0f + erff(z * 0.70710678118654752f));
        f += g * ffn_w2[j];
    }
    out[0] = o + f;
}

__global__ void hf_kernel(const float* __restrict__ acc, const float* __restrict__ b1,
                          const float* __restrict__ Cs, float* __restrict__ hf) {
    int g = blockIdx.x * blockDim.x + threadIdx.x;
    int row = g >> 5;
    int lane = g & 31;
    if (row >= NPAP) return;
    float C = Cs[0];
    long long base = (long long)row * HID;
    float v0 = acc[base + lane]      + b1[lane]      + b1[64 + lane];
    float v1 = acc[base + lane + 32] + b1[lane + 32] + b1[96 + lane];
    float w0 = v0 + C, w1 = v1 + C;
    float s1 = v0 * v0 + v1 * v1;
    float s2 = w0 * w0 + w1 * w1;
#pragma unroll
    for (int o = 16; o; o >>= 1) {
        s1 += __shfl_xor_sync(0xFFFFFFFFu, s1, o);
        s2 += __shfl_xor_sync(0xFFFFFFFFu, s2, o);
    }
    float i1 = 1.f / fmaxf(sqrtf(s1), 1e-12f);
    float i2 = 1.f / fmaxf(sqrtf(s2), 1e-12f);
    long long hb = (long long)row * 128;
    hf[hb + lane]       = v0 * i1;
    hf[hb + lane + 32]  = v1 * i1;
    hf[hb + 64 + lane]  = w0 * i2;
    hf[hb + 96 + lane]  = w1 * i2;
}

// ---------------------------------------------------------------------------
extern "C" void kernel_launch(void* const* d_in, const int* in_sizes, int n_in,
                              void* d_out, int out_size) {
    const float* x_author = (const float*)d_in[0];
    const float* x_paper  = (const float*)d_in[1];
    const float* ntype    = (const float*)d_in[2];
    const float* W0       = (const float*)d_in[3];
    const float* al0      = (const float*)d_in[4];
    const float* ar0      = (const float*)d_in[5];
    const float* b0       = (const float*)d_in[6];
    const float* W1       = (const float*)d_in[7];
    const float* al1      = (const float*)d_in[8];
    const float* ar1      = (const float*)d_in[9];
    const float* b1       = (const float*)d_in[10];
    const float* ln1_gb   = (const float*)d_in[11];
    const float* attn_w   = (const float*)d_in[12];
    const float* attn_b   = (const float*)d_in[13];
    const float* ln2_gb   = (const float*)d_in[14];
    const float* ffn_w1   = (const float*)d_in[15];
    const float* ffn_b1   = (const float*)d_in[16];
    const float* ffn_w2   = (const float*)d_in[17];
    const float* ffn_b2   = (const float*)d_in[18];
    const float* lin_W    = (const float*)d_in[19];
    const float* lin_b    = (const float*)d_in[20];
    const int* src_w = (const int*)d_in[21];
    const int* dst_w = (const int*)d_in[22];
    const int* src_c = (const int*)d_in[23];
    const int* dst_c = (const int*)d_in[24];
    const int* src_r = (const int*)d_in[25];
    const int* dst_r = (const int*)d_in[26];
    float* out = (float*)d_out;

    float* S = nullptr;
    cudaGetSymbolAddress((void**)&S, g_scratch);

    float* Fa0  = S + OFF_FA0;
    float* Fp0  = S + OFF_FP0;
    float* Fp1  = S + OFF_FP1;
    float* Fp2  = S + OFF_FP2;
    float* Fa2  = S + OFF_FA2;
    float* F1a  = S + OFF_F1A;
    float* F1pd = S + OFF_F1PD;
    float* F1pc = S + OFF_F1PC;
    float* outp  = S + OFF_OUTP;
    float* outp1 = S + OFF_OUTP1;
    float* ha1  = S + OFF_HA1;
    float* hp1  = S + OFF_HP1;
    float* hf   = S + OFF_HF;
    float* el_w = S + OFF_ELER + 0 * N4;
    float* er_w = S + OFF_ELER + 1 * N4;
    float* el_c = S + OFF_ELER + 2 * N4;
    float* er_c = S + OFF_ELER + 3 * N4;
    float* el_r = S + OFF_ELER + 4 * N4;
    float* er_r = S + OFF_ELER + 5 * N4;
    float* el1w = S + OFF_ELER + 6 * N4;
    float* er1w = S + OFF_ELER + 7 * N4;
    float* el1c = S + OFF_ELER + 8 * N4;
    float* er1c = S + OFF_ELER + 9 * N4;
    float* Cscalar = S + OFF_C;
    int* degB = (int*)(S + OFF_DEG);
    int* rpB  = (int*)(S + OFF_RP);
    int* csrB = (int*)(S + OFF_CSR);

    const int T = 256;

    // ---- CSR build ----
    zero_int_kernel<<<(3 * NNODE + T - 1) / T, T>>>(degB, 3 * NNODE);
    hist3_kernel<<<(3 * NEDGE + T - 1) / T, T>>>(dst_w, dst_c, dst_r, degB);
    scan3_kernel<<<3, 1024>>>(degB, rpB);
    scatter3_kernel<<<(3 * NEDGE + T - 1) / T, T>>>(src_w, dst_w, src_c, dst_c,
                                                    src_r, dst_r, degB, csrB);
    const int* rp_w = rpB + 0 * (NNODE + 1);
    const int* rp_c = rpB + 1 * (NNODE + 1);
    const int* rp_r = rpB + 2 * (NNODE + 1);
    const int* csr_w = csrB + 0LL * NEDGE;
    const int* csr_c = csrB + 1LL * NEDGE;
    const int* csr_r = csrB + 2LL * NEDGE;

    // ---- layer 0: 5 GEMMs batched (ntype scale fused) ----
    Gemm5 g0;
    g0.A[0] = x_author; g0.scale[0] = ntype;          g0.W[0] = W0 + 0 * 8192; g0.C[0] = Fa0;
    g0.A[1] = x_paper;  g0.scale[1] = ntype + IN_DIM; g0.W[1] = W0 + 0 * 8192; g0.C[1] = Fp0;
    g0.A[2] = x_paper;  g0.scale[2] = ntype + IN_DIM; g0.W[2] = W0 + 1 * 8192; g0.C[2] = Fp1;
    g0.A[3] = x_paper;  g0.scale[3] = ntype + IN_DIM; g0.W[3] = W0 + 2 * 8192; g0.C[3] = Fp2;
    g0.A[4] = x_author; g0.scale[4] = ntype;          g0.W[4] = W0 + 2 * 8192; g0.C[4] = Fa2;
    g0.K = IN_DIM;
    gemm128_kernel<<<dim3(NNODE / 128, 5), 256>>>(g0);

    Eler6 e0;
    e0.F[0] = Fa0; e0.a[0] = al0 + 0 * 64; e0.out[0] = el_w;
    e0.F[1] = Fp0; e0.a[1] = ar0 + 0 * 64; e0.out[1] = er_w;
    e0.F[2] = Fp1; e0.a[2] = al0 + 1 * 64; e0.out[2] = el_c;
    e0.F[3] = Fp1; e0.a[3] = ar0 + 1 * 64; e0.out[3] = er_c;
    e0.F[4] = Fp2; e0.a[4] = al0 + 2 * 64; e0.out[4] = el_r;
    e0.F[5] = Fa2; e0.a[5] = ar0 + 2 * 64; e0.out[5] = er_r;
    eler_kernel<<<dim3((int)(N4 / T), 6), T>>>(e0);

    unsigned gb = (2 * NNODE * 32) / T;     // two warps per dst node
    gat_kernel<<<gb, T>>>(rp_w, csr_w, el_w, er_w, Fa0, nullptr, nullptr, nullptr, 0, outp);
    gat_kernel<<<gb, T>>>(rp_r, csr_r, el_r, er_r, Fp2, nullptr, b0 + 128, nullptr, 1, ha1);
    gat_kernel<<<gb, T>>>(rp_c, csr_c, el_c, er_c, Fp1, outp, b0, b0 + 64, 1, hp1);

    // ---- layer 1: 3 GEMMs batched ----
    Gemm5 g1;
    g1.A[0] = ha1; g1.scale[0] = nullptr; g1.W[0] = W1 + 0 * 4096; g1.C[0] = F1a;
    g1.A[1] = hp1; g1.scale[1] = nullptr; g1.W[1] = W1 + 0 * 4096; g1.C[1] = F1pd;
    g1.A[2] = hp1; g1.scale[2] = nullptr; g1.W[2] = W1 + 1 * 4096; g1.C[2] = F1pc;
    g1.A[3] = g1.A[4] = nullptr; g1.scale[3] = g1.scale[4] = nullptr;
    g1.W[3] = g1.W[4] = nullptr; g1.C[3] = g1.C[4] = nullptr;
    g1.K = HID;
    gemm128_kernel<<<dim3(NNODE / 128, 3), 256>>>(g1);

    Eler6 e1;
    e1.F[0] = F1a;  e1.a[0] = al1 + 0 * 64; e1.out[0] = el1w;
    e1.F[1] = F1pd; e1.a[1] = ar1 + 0 * 64; e1.out[1] = er1w;
    e1.F[2] = F1pc; e1.a[2] = al1 + 1 * 64; e1.out[2] = el1c;
    e1.F[3] = F1pc; e1.a[3] = ar1 + 1 * 64; e1.out[3] = er1c;
    e1.F[4] = e1.F[5] = nullptr; e1.a[4] = e1.a[5] = nullptr; e1.out[4] = e1.out[5] = nullptr;
    eler_kernel<<<dim3((int)(N4 / T), 4), T>>>(e1);

    gat_kernel<<<gb, T>>>(rp_w, csr_w, el1w, er1w, F1a, nullptr, nullptr, nullptr, 0, outp1);
    gat_kernel<<<gb, T>>>(rp_c, csr_c, el1c, er1c, F1pc, outp1, nullptr, nullptr, 0, outp1);

    compute_C_kernel<<<1, 1>>>(ln1_gb, attn_w, attn_b, ln2_gb,
                               ffn_w1, ffn_b1, ffn_w2, ffn_b2, Cscalar);
    hf_kernel<<<(NPAP * 32) / T, T>>>(outp1, b1, Cscalar, hf);

    gemm_full_kernel<<<dim3(NPAP / 128, (OUTF + 63) / 64), 256>>>(hf, lin_W, lin_b, out,
                                                                  2 * HID, OUTF);
}